// round 3
// baseline (speedup 1.0000x reference)
#include <cuda_runtime.h>
#include <cstdint>

// ---------------- problem constants ----------------
#define SEQA   4096
#define BATCH  8
#define DM     1024
#define NHEADS 16
#define HD     64
#define MROWS  (SEQA*BATCH)   // 32768

// ---------------- scratch (device globals; no allocation allowed) ----------
__device__ float g_Q[(size_t)MROWS * DM];
__device__ float g_K[(size_t)MROWS * DM];
__device__ float g_V[(size_t)MROWS * DM];
__device__ float g_X[(size_t)MROWS * DM];

// ---------------- helpers ----------------
__device__ __forceinline__ uint32_t f2tf32(float f) {
    uint32_t u;
    asm("cvt.rna.tf32.f32 %0, %1;" : "=r"(u) : "f"(f));
    return u;
}

__device__ __forceinline__ void mma_tf32(float c[4],
                                         uint32_t a0, uint32_t a1, uint32_t a2, uint32_t a3,
                                         uint32_t b0, uint32_t b1) {
    asm volatile(
        "mma.sync.aligned.m16n8k8.row.col.f32.tf32.tf32.f32 "
        "{%0,%1,%2,%3}, {%4,%5,%6,%7}, {%8,%9}, {%0,%1,%2,%3};"
        : "+f"(c[0]), "+f"(c[1]), "+f"(c[2]), "+f"(c[3])
        : "r"(a0), "r"(a1), "r"(a2), "r"(a3), "r"(b0), "r"(b1));
}

__device__ __forceinline__ void cp_async16(void* smem_dst, const void* gmem_src) {
    uint32_t s = (uint32_t)__cvta_generic_to_shared(smem_dst);
    asm volatile("cp.async.cg.shared.global [%0], [%1], 16;" :: "r"(s), "l"(gmem_src));
}
__device__ __forceinline__ void cp_async_commit() {
    asm volatile("cp.async.commit_group;");
}
template <int N>
__device__ __forceinline__ void cp_async_wait() {
    asm volatile("cp.async.wait_group %0;" :: "n"(N));
}

// ---------------- TF32 GEMM: C = A(M,K) * W(N,K)^T + bias ----------------
// cp.async double-buffered. Raw f32 staged in smem; tf32 conversion at
// fragment load.
// mode 0: C row = m           (QKV projections)
// mode 1: C row = (m&4095)*8 + (m>>12)   (final output permutation)
#define BM 128
#define BN 128
#define BK 32
#define KPAD 36          // 36 floats = 144B row stride (16B-aligned)
#define TILE_F (BM * KPAD)
#define NTILES (DM / BK) // 32

__global__ __launch_bounds__(256) void gemm_tf32(
    const float* __restrict__ A, const float* __restrict__ W,
    const float* __restrict__ bias, float* __restrict__ C, int mode)
{
    extern __shared__ float smem[];
    float* sA = smem;                 // [2][BM][KPAD]
    float* sB = smem + 2 * TILE_F;    // [2][BN][KPAD]

    const int tid = threadIdx.x;
    const int m0 = blockIdx.y * BM;
    const int n0 = blockIdx.x * BN;
    const int w = tid >> 5, lane = tid & 31;
    const int wm = w & 1;        // 0..1 -> 64-row warp tile
    const int wn = w >> 1;       // 0..3 -> 32-col warp tile
    const int gid = lane >> 2, tq = lane & 3;

    // per-thread staging coordinates: 4 chunks of 16B for A, 4 for B
    // idx = i*256+tid ; r = idx>>3 ; c4 = (idx&7)*4
    float acc[4][4][4];
#pragma unroll
    for (int i = 0; i < 4; i++)
#pragma unroll
        for (int j = 0; j < 4; j++)
#pragma unroll
            for (int k = 0; k < 4; k++) acc[i][j][k] = 0.f;

    // ---- prefetch tile 0 ----
    {
        const int k0 = 0;
#pragma unroll
        for (int i = 0; i < 4; i++) {
            int idx = i * 256 + tid;
            int r = idx >> 3;
            int c4 = (idx & 7) << 2;
            cp_async16(&sA[r * KPAD + c4], A + (size_t)(m0 + r) * DM + k0 + c4);
            cp_async16(&sB[r * KPAD + c4], W + (size_t)(n0 + r) * DM + k0 + c4);
        }
        cp_async_commit();
    }

    for (int t = 0; t < NTILES; t++) {
        // issue prefetch of tile t+1 into the other buffer
        if (t + 1 < NTILES) {
            const int k0 = (t + 1) * BK;
            float* dA = sA + ((t + 1) & 1) * TILE_F;
            float* dB = sB + ((t + 1) & 1) * TILE_F;
#pragma unroll
            for (int i = 0; i < 4; i++) {
                int idx = i * 256 + tid;
                int r = idx >> 3;
                int c4 = (idx & 7) << 2;
                cp_async16(&dA[r * KPAD + c4], A + (size_t)(m0 + r) * DM + k0 + c4);
                cp_async16(&dB[r * KPAD + c4], W + (size_t)(n0 + r) * DM + k0 + c4);
            }
            cp_async_commit();
            cp_async_wait<1>();
        } else {
            cp_async_wait<0>();
        }
        __syncthreads();

        const float* cA = sA + (t & 1) * TILE_F;
        const float* cB = sB + (t & 1) * TILE_F;

#pragma unroll
        for (int kk = 0; kk < BK; kk += 8) {
            uint32_t af[4][4], bf[4][2];
#pragma unroll
            for (int mi = 0; mi < 4; mi++) {
                int row = wm * 64 + mi * 16 + gid;
                af[mi][0] = f2tf32(cA[row * KPAD + kk + tq]);
                af[mi][1] = f2tf32(cA[(row + 8) * KPAD + kk + tq]);
                af[mi][2] = f2tf32(cA[row * KPAD + kk + tq + 4]);
                af[mi][3] = f2tf32(cA[(row + 8) * KPAD + kk + tq + 4]);
            }
#pragma unroll
            for (int ni = 0; ni < 4; ni++) {
                int col = wn * 32 + ni * 8 + gid;
                bf[ni][0] = f2tf32(cB[col * KPAD + kk + tq]);
                bf[ni][1] = f2tf32(cB[col * KPAD + kk + tq + 4]);
            }
#pragma unroll
            for (int mi = 0; mi < 4; mi++)
#pragma unroll
                for (int ni = 0; ni < 4; ni++)
                    mma_tf32(acc[mi][ni],
                             af[mi][0], af[mi][1], af[mi][2], af[mi][3],
                             bf[ni][0], bf[ni][1]);
        }
        __syncthreads();   // all threads done reading buf (t&1) before next
                           // iteration's prefetch overwrites it
    }

    // epilogue: add bias, apply row permutation, store
#pragma unroll
    for (int mi = 0; mi < 4; mi++) {
#pragma unroll
        for (int ni = 0; ni < 4; ni++) {
            int row0 = m0 + wm * 64 + mi * 16 + gid;
            int row1 = row0 + 8;
            int col = n0 + wn * 32 + ni * 8 + tq * 2;
            float bb0 = bias[col], bb1 = bias[col + 1];
            size_t or0 = mode ? (size_t)((row0 & 4095) * 8 + (row0 >> 12)) : (size_t)row0;
            size_t or1 = mode ? (size_t)((row1 & 4095) * 8 + (row1 >> 12)) : (size_t)row1;
            C[or0 * DM + col]     = acc[mi][ni][0] + bb0;
            C[or0 * DM + col + 1] = acc[mi][ni][1] + bb1;
            C[or1 * DM + col]     = acc[mi][ni][2] + bb0;
            C[or1 * DM + col + 1] = acc[mi][ni][3] + bb1;
        }
    }
}

#define GEMM_SMEM (4 * TILE_F * (int)sizeof(float))   // 73728 bytes

// ---------------- per-position head-mixing attention + sparsemax ------------
// one block per (a,b) position; scores are 16x16 over HEADS.
__global__ __launch_bounds__(256) void attn_kernel(
    const float* __restrict__ Q, const float* __restrict__ K,
    const float* __restrict__ V, float* __restrict__ X)
{
    const int pos = blockIdx.x;            // pos = a*BATCH + b
    const int a = pos >> 3, b = pos & 7;
    const int tid = threadIdx.x;

    __shared__ float Qs[NHEADS][HD + 1];
    __shared__ float Ks[NHEADS][HD + 1];
    __shared__ float Vs[NHEADS][HD];
    __shared__ float Ss[NHEADS][NHEADS];
    __shared__ float At[NHEADS][NHEADS];

    const float* qrow = Q + (size_t)pos * DM;
    const float* krow = K + (size_t)pos * DM;
    const float* vrow = V + (size_t)pos * DM;
    for (int i = tid; i < DM; i += 256) {
        int hh = i >> 6, dd = i & 63;
        Qs[hh][dd] = qrow[i];
        Ks[hh][dd] = krow[i];
        Vs[hh][dd] = vrow[i];
    }
    __syncthreads();

    // scores: thread (h,g) computes dot over HD, scaled by 1/(sqrt(64)*alpha)=1/12
    {
        int h = tid >> 4, g = tid & 15;
        float s = 0.f;
#pragma unroll
        for (int d = 0; d < HD; d++) s += Qs[h][d] * Ks[g][d];
        Ss[h][g] = s * (1.0f / 12.0f);
    }
    __syncthreads();

    // sparsemax per head row (16 values) — threads 0..15
    if (tid < NHEADS) {
        float z[16], zs[16], cum[16];
#pragma unroll
        for (int g = 0; g < 16; g++) { z[g] = Ss[tid][g]; zs[g] = z[g]; }
        for (int i = 1; i < 16; i++) {        // insertion sort descending
            float key = zs[i];
            int j = i - 1;
            while (j >= 0 && zs[j] < key) { zs[j + 1] = zs[j]; j--; }
            zs[j + 1] = key;
        }
        float c = 0.f;
        int cnt = 0;
        for (int i = 0; i < 16; i++) {
            c += zs[i];
            cum[i] = c;
            if (zs[i] - (c - 1.0f) / (float)(i + 1) > 0.f) cnt++;
        }
        if (cnt < 1) cnt = 1;
        float tau = (cum[cnt - 1] - 1.0f) / (float)cnt;
#pragma unroll
        for (int g = 0; g < 16; g++) At[tid][g] = fmaxf(z[g] - tau, 0.f);
    }
    __syncthreads();

    // attn_out[h][d] = sum_g At[h][g] * V[g][d], written in permuted layout:
    // X[b][h*256 + a/16][(a%16)*64 + d]   (X is (BATCH, 4096, DM) contiguous)
    const size_t xbase = (size_t)b * SEQA * DM + (size_t)(a >> 4) * DM + (size_t)(a & 15) * HD;
    for (int i = tid; i < DM; i += 256) {
        int hh = i >> 6, dd = i & 63;
        float o = 0.f;
#pragma unroll
        for (int g = 0; g < 16; g++) o += At[hh][g] * Vs[g][dd];
        X[xbase + (size_t)hh * 256 * DM + dd] = o;
    }
}

// ---------------- launch ----------------
extern "C" void kernel_launch(void* const* d_in, const int* in_sizes, int n_in,
                              void* d_out, int out_size)
{
    const float* query = (const float*)d_in[0];
    const float* key   = (const float*)d_in[1];
    const float* value = (const float*)d_in[2];
    const float* Wq = (const float*)d_in[3];
    const float* bq = (const float*)d_in[4];
    const float* Wk = (const float*)d_in[5];
    const float* bk = (const float*)d_in[6];
    const float* Wv = (const float*)d_in[7];
    const float* bv = (const float*)d_in[8];
    const float* Wo = (const float*)d_in[9];
    const float* bo = (const float*)d_in[10];
    float* out = (float*)d_out;

    float *pQ, *pK, *pV, *pX;
    cudaGetSymbolAddress((void**)&pQ, g_Q);
    cudaGetSymbolAddress((void**)&pK, g_K);
    cudaGetSymbolAddress((void**)&pV, g_V);
    cudaGetSymbolAddress((void**)&pX, g_X);

    // dynamic smem 73728B > 48KB default: opt in (host config call, not a
    // stream op — graph-capture safe, idempotent)
    cudaFuncSetAttribute(gemm_tf32, cudaFuncAttributeMaxDynamicSharedMemorySize,
                         GEMM_SMEM);

    dim3 grid(DM / BN, MROWS / BM);   // (8, 256)
    gemm_tf32<<<grid, 256, GEMM_SMEM>>>(query, Wq, bq, pQ, 0);
    gemm_tf32<<<grid, 256, GEMM_SMEM>>>(key,   Wk, bk, pK, 0);
    gemm_tf32<<<grid, 256, GEMM_SMEM>>>(value, Wv, bv, pV, 0);
    attn_kernel<<<MROWS, 256>>>(pQ, pK, pV, pX);
    gemm_tf32<<<grid, 256, GEMM_SMEM>>>(pX, Wo, bo, out, 1);
}